// round 11
// baseline (speedup 1.0000x reference)
#include <cuda_runtime.h>

#define INV_CELL 20.0f
#define NTHREADS 256     // 8 warps; 8 threads per point -> 32 points per block
#define PTS 32

// Cubic B-spline basis + gradient for a single stencil offset m (0..3).
// x = f + 1 - m deterministically falls in branch: m=0 -> [1,2), m=1 -> [0,1),
// m=2 -> [-1,0), m=3 -> [-2,-1). Coefficients compile-time (m unrolled);
// FMA chains identical in shape to the reference polynomials.
__device__ __forceinline__ void spline1(float f, int m, float& b, float& db) {
    float x  = f + (float)(1 - m);
    float a3 = (m == 0) ? -1.0f/6.0f : (m == 1) ? 0.5f : (m == 2) ? -0.5f : 1.0f/6.0f;
    float a2 = (m == 0 || m == 3) ? 1.0f : -1.0f;
    float a1 = (m == 0) ? -2.0f : (m == 3) ? 2.0f : 0.0f;
    float a0 = (m == 0 || m == 3) ? 4.0f/3.0f : 2.0f/3.0f;
    float d2 = (m == 0) ? -0.5f : (m == 1) ? 1.5f : (m == 2) ? -1.5f : 0.5f;
    float d1 = (m == 0 || m == 3) ? 2.0f : -2.0f;
    float d0 = (m == 0) ? -2.0f : (m == 3) ? 2.0f : 0.0f;
    b  = ((a3 * x + a2) * x + a1) * x + a0;
    db = INV_CELL * ((d2 * x + d1) * x + d0);
}

// Branch-free 4-way select (2 predicates + 3 SELs).
__device__ __forceinline__ float sel4(const float a[4], int m) {
    float lo = (m & 1) ? a[1] : a[0];
    float hi = (m & 1) ? a[3] : a[2];
    return (m & 2) ? hi : lo;
}

// Gradient components of stencil entry e (0..63): e = (i<<4)|(j<<2)|k.
__device__ __forceinline__ void entry_grad(int e,
        const float bx[4], const float dbx[4],
        const float by[4], const float dby[4],
        const float bz[4], const float dbz[4],
        float& c0, float& c1, float& c2) {
    int i = (e >> 4) & 3, j = (e >> 2) & 3, k = e & 3;
    float BX = sel4(bx, i), DBX = sel4(dbx, i);
    float BY = sel4(by, j), DBY = sel4(dby, j);
    float BZ = sel4(bz, k), DBZ = sel4(dbz, k);
    c0 = (DBX * BY) * BZ;
    c1 = (BX * DBY) * BZ;
    c2 = (BX * BY) * DBZ;
}

__global__ void __launch_bounds__(NTHREADS, 5)
cubic_shape_kernel(const float* __restrict__ pos,
                   float* __restrict__ out_sf,
                   float* __restrict__ out_grad,
                   int n_points) {
    int tid = threadIdx.x;
    int g   = tid >> 3;        // local point
    int s   = tid & 7;         // sub-thread within point
    int n   = blockIdx.x * PTS + g;
    if (n >= n_points) return;

    float px = __ldg(&pos[n * 3 + 0]);
    float py = __ldg(&pos[n * 3 + 1]);
    float pz = __ldg(&pos[n * 3 + 2]);

    float rx = px * INV_CELL, ry = py * INV_CELL, rz = pz * INV_CELL;
    float fx = rx - floorf(rx);
    float fy = ry - floorf(ry);
    float fz = rz - floorf(rz);

    // full spline table: 24 values
    float bx[4], dbx[4], by[4], dby[4], bz[4], dbz[4];
#pragma unroll
    for (int m = 0; m < 4; m++) {
        spline1(fx, m, bx[m], dbx[m]);
        spline1(fy, m, by[m], dby[m]);
        spline1(fz, m, bz[m], dbz[m]);
    }

    // ---- sf: direct stores, thread owns float4 {s, s+8} ----
    // q = 4*i + j: q1=s -> i=s>>2, j=s&3 ; q2=s+8 -> i=(s>>2)+2, j=s&3
    {
        int   iq  = s >> 2;
        int   jq  = s & 3;
        float byq = sel4(by, jq);
        float bxa = iq ? bx[1] : bx[0];
        float bxb = iq ? bx[3] : bx[2];
        float va  = bxa * byq;
        float vb  = bxb * byq;
        float4* sfp = reinterpret_cast<float4*>(out_sf) + (size_t)n * 16;
        __stcs(&sfp[s],     make_float4(va * bz[0], va * bz[1], va * bz[2], va * bz[3]));
        __stcs(&sfp[s + 8], make_float4(vb * bz[0], vb * bz[1], vb * bz[2], vb * bz[3]));
    }

    // ---- grad: direct stores, thread owns float4 {s + 8p, p=0..5} ----
    // float4 q covers floats 4q..4q+3 of the point's 192-float grad block:
    // entries e0=(4q)/3 and e0+1, with component phase ph = q%3.
    {
        float4* gdst = reinterpret_cast<float4*>(out_grad) + (size_t)n * 48;
#pragma unroll
        for (int p = 0; p < 6; p++) {
            int q  = s + 8 * p;
            int e0 = (4 * q) / 3;
            int ph = q % 3;

            float c00, c01, c02, c10, c11, c12;
            entry_grad(e0,     bx, dbx, by, dby, bz, dbz, c00, c01, c02);
            entry_grad(e0 + 1, bx, dbx, by, dby, bz, dbz, c10, c11, c12);

            bool p0 = (ph == 0), p1 = (ph == 1);
            float4 v;
            v.x = p0 ? c00 : (p1 ? c01 : c02);
            v.y = p0 ? c01 : (p1 ? c02 : c10);
            v.z = p0 ? c02 : (p1 ? c10 : c11);
            v.w = p0 ? c10 : (p1 ? c11 : c12);
            __stcs(&gdst[q], v);
        }
    }
}

extern "C" void kernel_launch(void* const* d_in, const int* in_sizes, int n_in,
                              void* d_out, int out_size) {
    const float* pos = (const float*)d_in[0];
    int n_points = in_sizes[0] / 3;

    float* out_sf   = (float*)d_out;                      // [N, 64]
    float* out_grad = out_sf + (size_t)n_points * 64;     // [N, 64, 3]

    int grid = (n_points + PTS - 1) / PTS;
    cubic_shape_kernel<<<grid, NTHREADS>>>(pos, out_sf, out_grad, n_points);
}